// round 15
// baseline (speedup 1.0000x reference)
#include <cuda_runtime.h>
#include <cuda_bf16.h>
#include <cstdint>
#include <cstddef>

#define BT 2048
#define HS 2048
#define HT 4096
#define VV 32000
#define IGNORE_IDX (-100)

#define BM 128
#define BN 256
#define BK 128                    // fp8 elems per K-tile = 128 bytes per row
#define THREADS 512
#define STAGES 3
#define KT_S (HS / BK)            // 16 student K-tiles
#define KT_T (HT / BK)            // 32 teacher K-tiles
#define A_BYTES (BM * 128)        // 16384
#define B_BYTES (BN * 128)        // 32768
#define STAGE_BYTES (A_BYTES + B_BYTES)          // 49152
#define SMEM_BYTES (STAGES * STAGE_BYTES)        // 147456

#define WSCALE 64.0f              // weight scale before fp8 quantization (2^6)
#define ISCALE (1.0f / 64.0f)     // logit un-scale in epilogue

#define SWZ(x) ((x) ^ (((x) >> 3) & 0x70))

// ---------------- scratch ------------------------------------------------------
__device__ __align__(16) uint8_t g_s8[(size_t)BT * HS];
__device__ __align__(16) uint8_t g_t8[(size_t)BT * HT];
__device__ __align__(16) uint8_t g_sw8[(size_t)VV * HS];
__device__ __align__(16) uint8_t g_tw8[(size_t)VV * HT];
// student-logit stash: bf16, FLAT [row][col] layout (row-major, col even pairs)
__device__ __align__(16) __nv_bfloat162 g_stashb[(size_t)BT * VV / 2];

__device__ float g_sumexp[BT];
__device__ float g_ss[BT];
__device__ float g_tt[BT];
__device__ float g_st[BT];
__device__ float g_tgt[BT];

// ---------------- asm helpers ------------------------------------------------
__device__ __forceinline__ uint32_t smem_u32(const void* p) {
    uint32_t a;
    asm("{ .reg .u64 t; cvta.to.shared.u64 t, %1; cvt.u32.u64 %0, t; }" : "=r"(a) : "l"(p));
    return a;
}
__device__ __forceinline__ void cp_async16(uint32_t dst, const void* src) {
    asm volatile("cp.async.cg.shared.global [%0], [%1], 16;" :: "r"(dst), "l"(src) : "memory");
}
__device__ __forceinline__ void cp_commit() {
    asm volatile("cp.async.commit_group;" ::: "memory");
}
__device__ __forceinline__ void ldsm_x4(uint32_t* r, uint32_t addr) {
    asm volatile("ldmatrix.sync.aligned.m8n8.x4.shared.b16 {%0,%1,%2,%3}, [%4];"
                 : "=r"(r[0]), "=r"(r[1]), "=r"(r[2]), "=r"(r[3]) : "r"(addr));
}
__device__ __forceinline__ void mma16832(float* d, const uint32_t* a, uint32_t b0, uint32_t b1) {
    asm volatile(
        "mma.sync.aligned.m16n8k32.row.col.f32.e4m3.e4m3.f32 "
        "{%0,%1,%2,%3}, {%4,%5,%6,%7}, {%8,%9}, {%0,%1,%2,%3};"
        : "+f"(d[0]), "+f"(d[1]), "+f"(d[2]), "+f"(d[3])
        : "r"(a[0]), "r"(a[1]), "r"(a[2]), "r"(a[3]), "r"(b0), "r"(b1));
}
__device__ __forceinline__ uint32_t pack_e4m3_4(float a, float b, float c, float d) {
    uint16_t lo, hi;
    asm("cvt.rn.satfinite.e4m3x2.f32 %0, %1, %2;" : "=h"(lo) : "f"(b), "f"(a));
    asm("cvt.rn.satfinite.e4m3x2.f32 %0, %1, %2;" : "=h"(hi) : "f"(d), "f"(c));
    return (uint32_t)lo | ((uint32_t)hi << 16);
}

// ---------------- Kernel: dual fp32 -> fp8 convert ---------------------------
// pair==0: teacher act + teacher weights -> g_t8, g_tw8
// pair==1: student act + student weights -> g_s8, g_sw8 (also zeroes accums)
// Output pointers resolved IN DEVICE CODE (host-side &__device__ symbol is the
// host shadow address — the R11-R14 correctness bug).
__global__ void cvt2_kernel(const float4* __restrict__ in0, size_t n0, float sc0,
                            const float4* __restrict__ in1, size_t n1, float sc1,
                            int pair) {
    uint32_t* out0;
    uint32_t* out1;
    if (pair == 0) { out0 = (uint32_t*)g_t8; out1 = (uint32_t*)g_tw8; }
    else           { out0 = (uint32_t*)g_s8; out1 = (uint32_t*)g_sw8; }
    if (pair == 1) {
        int gid = blockIdx.x * blockDim.x + threadIdx.x;
        if (gid < BT) {
            g_sumexp[gid] = 0.f; g_ss[gid] = 0.f; g_tt[gid] = 0.f; g_st[gid] = 0.f;
        }
    }
    size_t stride = (size_t)gridDim.x * blockDim.x;
    size_t total = n0 + n1;
    for (size_t i = (size_t)blockIdx.x * blockDim.x + threadIdx.x; i < total; i += stride) {
        const float4* in; uint32_t* out; size_t j; float sc;
        if (i < n0) { in = in0; out = out0; j = i; sc = sc0; }
        else        { in = in1; out = out1; j = i - n0; sc = sc1; }
        float4 v = in[j];
        out[j] = pack_e4m3_4(v.x * sc, v.y * sc, v.z * sc, v.w * sc);
    }
}

// ---------------- Kernel: exact fp32 target logit -----------------------------
__global__ void tgt_kernel(const float* __restrict__ student,
                           const float* __restrict__ sw,
                           const int* __restrict__ target) {
    int row = blockIdx.x;
    int t = target[row];
    int ct = (t < 0 || t >= VV) ? 0 : t;
    const float4* a = (const float4*)(student + (size_t)row * HS);
    const float4* b = (const float4*)(sw + (size_t)ct * HS);
    float p = 0.f;
    for (int k = threadIdx.x; k < HS / 4; k += blockDim.x) {
        float4 x = a[k]; float4 y = b[k];
        p += x.x * y.x + x.y * y.y + x.z * y.z + x.w * y.w;
    }
    __shared__ float sred[8];
    #pragma unroll
    for (int o = 16; o; o >>= 1) p += __shfl_down_sync(0xffffffffu, p, o);
    if ((threadIdx.x & 31) == 0) sred[threadIdx.x >> 5] = p;
    __syncthreads();
    if (threadIdx.x < 32) {
        p = (threadIdx.x < (blockDim.x >> 5)) ? sred[threadIdx.x] : 0.f;
        #pragma unroll
        for (int o = 16; o; o >>= 1) p += __shfl_down_sync(0xffffffffu, p, o);
        if (threadIdx.x == 0) g_tgt[row] = p;
    }
}

// ---------------- shared GEMM machinery (16 warps, 4m x 4n, 32x64 tiles) -----
struct GemmCtx {
    uint32_t sb;
    int wid, lane, mw, nw, q, r0;
    int rb, vb;
};

__device__ __forceinline__ void gemm_issue(const GemmCtx& c, const uint8_t* Ab,
                                           const uint8_t* Bb, int ldk, int kk, int s) {
    const uint32_t st = c.sb + s * STAGE_BYTES;
    #pragma unroll
    for (int cc = 0; cc < 2; cc++) {
        int row = c.r0 + 64 * cc;
        cp_async16(st + SWZ(row * 128 + c.q * 16),
                   Ab + (size_t)(c.rb + row) * ldk + kk * BK + c.q * 16);
    }
    #pragma unroll
    for (int cc = 0; cc < 4; cc++) {
        int row = c.r0 + 64 * cc;
        cp_async16(st + A_BYTES + SWZ(row * 128 + c.q * 16),
                   Bb + (size_t)(c.vb + row) * ldk + kk * BK + c.q * 16);
    }
    cp_commit();
}

__device__ __forceinline__ void gemm_step(const GemmCtx& c, const uint8_t* Ab,
                                          const uint8_t* Bb, int ldk, int kt, int nkt,
                                          float (&acc)[2][8][4]) {
    const int s = kt % STAGES;
    if (kt < nkt - 1) {
        asm volatile("cp.async.wait_group 1;" ::: "memory");
    } else {
        asm volatile("cp.async.wait_group 0;" ::: "memory");
    }
    __syncthreads();
    if (kt + 2 < nkt) gemm_issue(c, Ab, Bb, ldk, kt + 2, (kt + 2) % STAGES);

    const int arow = c.mw * 32 + (c.lane & 15);
    const int brow = c.nw * 64 + (c.lane & 15);
    const int csel = (c.lane >> 4) * 16;
    const uint32_t stA = c.sb + s * STAGE_BYTES;
    const uint32_t stB = stA + A_BYTES;
    #pragma unroll
    for (int kf = 0; kf < 4; kf++) {
        uint32_t af[2][4], bfv[4][4];
        #pragma unroll
        for (int mi = 0; mi < 2; mi++)
            ldsm_x4(af[mi], stA + SWZ((arow + mi * 16) * 128 + kf * 32 + csel));
        #pragma unroll
        for (int np = 0; np < 4; np++)
            ldsm_x4(bfv[np], stB + SWZ((brow + np * 16) * 128 + kf * 32 + csel));
        #pragma unroll
        for (int mi = 0; mi < 2; mi++)
            #pragma unroll
            for (int np = 0; np < 4; np++) {
                mma16832(acc[mi][2 * np + 0], af[mi], bfv[np][0], bfv[np][2]);
                mma16832(acc[mi][2 * np + 1], af[mi], bfv[np][1], bfv[np][3]);
            }
    }
}

// ---------------- Kernel: student GEMM -> sumexp/ss + bf16 flat stash --------
__global__ __launch_bounds__(THREADS, 1) void main_s_kernel() {
    extern __shared__ char smem[];
    GemmCtx c;
    c.sb = smem_u32(smem);
    int tid = threadIdx.x;
    c.wid = tid >> 5; c.lane = tid & 31;
    c.mw = c.wid & 3; c.nw = c.wid >> 2;
    c.q = tid & 7; c.r0 = tid >> 3;
    c.rb = blockIdx.x * BM; c.vb = blockIdx.y * BN;

    float acc[2][8][4];
    #pragma unroll
    for (int i = 0; i < 2; i++)
        #pragma unroll
        for (int j = 0; j < 8; j++)
            #pragma unroll
            for (int e = 0; e < 4; e++) acc[i][j][e] = 0.f;

    gemm_issue(c, g_s8, g_sw8, HS, 0, 0);
    gemm_issue(c, g_s8, g_sw8, HS, 1, 1);
    for (int kt = 0; kt < KT_S; kt++) gemm_step(c, g_s8, g_sw8, HS, kt, KT_S, acc);

    // epilogue: lane element (mi, hb, ni, e) is logit at
    //   row = rb + mw*32 + mi*16 + (lane>>2) + hb*8
    //   col = vb + nw*64 + ni*8 + (lane&3)*2 + e
    #pragma unroll
    for (int mi = 0; mi < 2; mi++) {
        #pragma unroll
        for (int hb = 0; hb < 2; hb++) {
            int row = c.rb + c.mw * 32 + mi * 16 + (c.lane >> 2) + hb * 8;
            int col0 = c.vb + c.nw * 64 + (c.lane & 3) * 2;
            size_t base2 = (size_t)row * (VV / 2) + (size_t)(col0 >> 1);
            float pe = 0.f, pss = 0.f;
            #pragma unroll
            for (int ni = 0; ni < 8; ni++) {
                float s0 = acc[mi][ni][hb * 2 + 0] * ISCALE;
                float s1 = acc[mi][ni][hb * 2 + 1] * ISCALE;
                pe += __expf(s0) + __expf(s1);
                pss += s0 * s0 + s1 * s1;
                g_stashb[base2 + (size_t)ni * 4] = __floats2bfloat162_rn(s0, s1);
            }
            #pragma unroll
            for (int o = 1; o < 4; o <<= 1) {
                pe += __shfl_xor_sync(0xffffffffu, pe, o);
                pss += __shfl_xor_sync(0xffffffffu, pss, o);
            }
            if ((c.lane & 3) == 0) {
                atomicAdd(&g_sumexp[row], pe);
                atomicAdd(&g_ss[row], pss);
            }
        }
    }
}

// ---------------- Kernel: teacher GEMM -> tt/st (reads flat stash) -----------
__global__ __launch_bounds__(THREADS, 1) void main_t_kernel() {
    extern __shared__ char smem[];
    GemmCtx c;
    c.sb = smem_u32(smem);
    int tid = threadIdx.x;
    c.wid = tid >> 5; c.lane = tid & 31;
    c.mw = c.wid & 3; c.nw = c.wid >> 2;
    c.q = tid & 7; c.r0 = tid >> 3;
    c.rb = blockIdx.x * BM; c.vb = blockIdx.y * BN;

    float acc[2][8][4];
    #pragma unroll
    for (int i = 0; i < 2; i++)
        #pragma unroll
        for (int j = 0; j < 8; j++)
            #pragma unroll
            for (int e = 0; e < 4; e++) acc[i][j][e] = 0.f;

    gemm_issue(c, g_t8, g_tw8, HT, 0, 0);
    gemm_issue(c, g_t8, g_tw8, HT, 1, 1);
    for (int kt = 0; kt < KT_T; kt++) gemm_step(c, g_t8, g_tw8, HT, kt, KT_T, acc);

    #pragma unroll
    for (int mi = 0; mi < 2; mi++) {
        #pragma unroll
        for (int hb = 0; hb < 2; hb++) {
            int row = c.rb + c.mw * 32 + mi * 16 + (c.lane >> 2) + hb * 8;
            int col0 = c.vb + c.nw * 64 + (c.lane & 3) * 2;
            size_t base2 = (size_t)row * (VV / 2) + (size_t)(col0 >> 1);
            float ptt = 0.f, pst = 0.f;
            #pragma unroll
            for (int ni = 0; ni < 8; ni++) {
                __nv_bfloat162 p = g_stashb[base2 + (size_t)ni * 4];
                float s0 = __bfloat162float(p.x);
                float s1 = __bfloat162float(p.y);
                float t0 = acc[mi][ni][hb * 2 + 0] * ISCALE;
                float t1 = acc[mi][ni][hb * 2 + 1] * ISCALE;
                ptt += t0 * t0 + t1 * t1;
                pst += s0 * t0 + s1 * t1;
            }
            #pragma unroll
            for (int o = 1; o < 4; o <<= 1) {
                ptt += __shfl_xor_sync(0xffffffffu, ptt, o);
                pst += __shfl_xor_sync(0xffffffffu, pst, o);
            }
            if ((c.lane & 3) == 0) {
                atomicAdd(&g_tt[row], ptt);
                atomicAdd(&g_st[row], pst);
            }
        }
    }
}

// ---------------- Kernel: final scalar loss ----------------------------------
__global__ void final_kernel(const int* __restrict__ target, float* __restrict__ out) {
    __shared__ float sh[16], ssf[16], snv[16];
    float hard = 0.f, soft = 0.f, nv = 0.f;
    for (int i = threadIdx.x; i < BT; i += blockDim.x) {
        int t = target[i];
        bool valid = (t != IGNORE_IDX);
        float lse = logf(g_sumexp[i]);
        if (valid) { hard += lse - g_tgt[i]; nv += 1.f; }
        float cs = g_st[i] * rsqrtf(g_ss[i] + 1e-12f) * rsqrtf(g_tt[i] + 1e-12f);
        soft += 1.f - cs;
    }
    #pragma unroll
    for (int o = 16; o; o >>= 1) {
        hard += __shfl_down_sync(0xffffffffu, hard, o);
        soft += __shfl_down_sync(0xffffffffu, soft, o);
        nv += __shfl_down_sync(0xffffffffu, nv, o);
    }
    int w = threadIdx.x >> 5, l = threadIdx.x & 31;
    if (l == 0) { sh[w] = hard; ssf[w] = soft; snv[w] = nv; }
    __syncthreads();
    if (threadIdx.x < 32) {
        int nw = blockDim.x >> 5;
        hard = (threadIdx.x < nw) ? sh[threadIdx.x] : 0.f;
        soft = (threadIdx.x < nw) ? ssf[threadIdx.x] : 0.f;
        nv = (threadIdx.x < nw) ? snv[threadIdx.x] : 0.f;
        #pragma unroll
        for (int o = 16; o; o >>= 1) {
            hard += __shfl_down_sync(0xffffffffu, hard, o);
            soft += __shfl_down_sync(0xffffffffu, soft, o);
            nv += __shfl_down_sync(0xffffffffu, nv, o);
        }
        if (threadIdx.x == 0)
            out[0] = 0.5f * hard / nv + 0.5f * soft / nv;
    }
}

// ---------------- launch ------------------------------------------------------
// Fork-join: side stream converts teacher inputs + computes tgt while the main
// stream converts student inputs and runs the student GEMM. Join before main_t.
extern "C" void kernel_launch(void* const* d_in, const int* in_sizes, int n_in,
                              void* d_out, int out_size) {
    const float* student = (const float*)d_in[0];
    const float* teacher = (const float*)d_in[1];
    const int* target = (const int*)d_in[2];
    const float* sw = (const float*)d_in[3];
    const float* tw = (const float*)d_in[4];
    float* out = (float*)d_out;

    cudaFuncSetAttribute(main_s_kernel, cudaFuncAttributeMaxDynamicSharedMemorySize, SMEM_BYTES);
    cudaFuncSetAttribute(main_t_kernel, cudaFuncAttributeMaxDynamicSharedMemorySize, SMEM_BYTES);

    cudaStream_t side = 0;
    cudaEvent_t evFork = nullptr, evJoin = nullptr;
    bool forked = false;
    if (cudaStreamCreateWithFlags(&side, cudaStreamNonBlocking) == cudaSuccess) {
        if (cudaEventCreateWithFlags(&evFork, cudaEventDisableTiming) == cudaSuccess &&
            cudaEventCreateWithFlags(&evJoin, cudaEventDisableTiming) == cudaSuccess) {
            forked = (cudaEventRecord(evFork, 0) == cudaSuccess) &&
                     (cudaStreamWaitEvent(side, evFork, 0) == cudaSuccess);
        }
    }
    cudaStream_t sideq = forked ? side : (cudaStream_t)0;

    // side: teacher-path conversions + exact target logit (hidden under main_s)
    cvt2_kernel<<<4096, 256, 0, sideq>>>(
        (const float4*)teacher, (size_t)BT * HT / 4, 1.0f,
        (const float4*)tw, (size_t)VV * HT / 4, WSCALE, /*pair=*/0);
    tgt_kernel<<<BT, 128, 0, sideq>>>(student, sw, target);
    if (forked) cudaEventRecord(evJoin, side);

    // main stream: student-path conversions (+ zero accs), student GEMM
    cvt2_kernel<<<4096, 256>>>(
        (const float4*)student, (size_t)BT * HS / 4, 1.0f,
        (const float4*)sw, (size_t)VV * HS / 4, WSCALE, /*pair=*/1);
    dim3 grid(BT / BM, VV / BN);  // (16, 125)
    main_s_kernel<<<grid, THREADS, SMEM_BYTES>>>();

    if (forked) cudaStreamWaitEvent(0, evJoin, 0);
    main_t_kernel<<<grid, THREADS, SMEM_BYTES>>>();
    final_kernel<<<1, 512>>>(target, out);
}

// round 16
// speedup vs baseline: 1.1141x; 1.1141x over previous
#include <cuda_runtime.h>
#include <cuda_bf16.h>
#include <cstdint>
#include <cstddef>

#define BT 2048
#define HS 2048
#define HT 4096
#define VV 32000
#define IGNORE_IDX (-100)

#define BM 128
#define BN 256
#define BK 128                    // fp8 elems per K-tile = 128 bytes per row
#define THREADS 512
#define STAGES 3
#define KT_S (HS / BK)            // 16 student K-tiles
#define KT_T (HT / BK)            // 32 teacher K-tiles
#define NKT (KT_S + KT_T)         // 48
#define A_BYTES (BM * 128)        // 16384
#define B_BYTES (BN * 128)        // 32768
#define STAGE_BYTES (A_BYTES + B_BYTES)          // 49152
#define SBUF_OFF (STAGES * STAGE_BYTES)          // 147456
#define SBUF_ROW 528                              // (256+8) bf16 -> conflict-free
#define SMEM_BYTES (SBUF_OFF + BM * SBUF_ROW)     // 215040

#define WSCALE 64.0f              // weight scale before fp8 quantization (2^6)
#define ISCALE (1.0f / 64.0f)     // logit un-scale in epilogue

#define SWZ(x) ((x) ^ (((x) >> 3) & 0x70))

// ---------------- fp8 scratch --------------------------------------------------
__device__ __align__(16) uint8_t g_s8[(size_t)BT * HS];
__device__ __align__(16) uint8_t g_t8[(size_t)BT * HT];
__device__ __align__(16) uint8_t g_sw8[(size_t)VV * HS];
__device__ __align__(16) uint8_t g_tw8[(size_t)VV * HT];

__device__ float g_sumexp[BT];
__device__ float g_ss[BT];
__device__ float g_tt[BT];
__device__ float g_st[BT];
__device__ float g_tgt[BT];

// ---------------- asm helpers ------------------------------------------------
__device__ __forceinline__ uint32_t smem_u32(const void* p) {
    uint32_t a;
    asm("{ .reg .u64 t; cvta.to.shared.u64 t, %1; cvt.u32.u64 %0, t; }" : "=r"(a) : "l"(p));
    return a;
}
__device__ __forceinline__ void cp_async16(uint32_t dst, const void* src) {
    asm volatile("cp.async.cg.shared.global [%0], [%1], 16;" :: "r"(dst), "l"(src) : "memory");
}
__device__ __forceinline__ void cp_commit() {
    asm volatile("cp.async.commit_group;" ::: "memory");
}
__device__ __forceinline__ void ldsm_x4(uint32_t* r, uint32_t addr) {
    asm volatile("ldmatrix.sync.aligned.m8n8.x4.shared.b16 {%0,%1,%2,%3}, [%4];"
                 : "=r"(r[0]), "=r"(r[1]), "=r"(r[2]), "=r"(r[3]) : "r"(addr));
}
// fp8 e4m3 MMA, K=32
__device__ __forceinline__ void mma16832(float* d, const uint32_t* a, uint32_t b0, uint32_t b1) {
    asm volatile(
        "mma.sync.aligned.m16n8k32.row.col.f32.e4m3.e4m3.f32 "
        "{%0,%1,%2,%3}, {%4,%5,%6,%7}, {%8,%9}, {%0,%1,%2,%3};"
        : "+f"(d[0]), "+f"(d[1]), "+f"(d[2]), "+f"(d[3])
        : "r"(a[0]), "r"(a[1]), "r"(a[2]), "r"(a[3]), "r"(b0), "r"(b1));
}
__device__ __forceinline__ uint32_t pack_e4m3_4(float a, float b, float c, float d) {
    uint16_t lo, hi;
    asm("cvt.rn.satfinite.e4m3x2.f32 %0, %1, %2;" : "=h"(lo) : "f"(b), "f"(a));
    asm("cvt.rn.satfinite.e4m3x2.f32 %0, %1, %2;" : "=h"(hi) : "f"(d), "f"(c));
    return (uint32_t)lo | ((uint32_t)hi << 16);
}

// ---------------- Kernel: fp32 -> fp8 (scaled); which==0 also zeroes accums --
// Output pointer resolved in DEVICE code (host &__device__ is a shadow address).
__global__ void cvt_kernel(const float4* __restrict__ in, int which, size_t n4, float scale) {
    if (which == 0) {
        int gid = blockIdx.x * blockDim.x + threadIdx.x;
        if (gid < BT) {
            g_sumexp[gid] = 0.f; g_ss[gid] = 0.f; g_tt[gid] = 0.f; g_st[gid] = 0.f;
        }
    }
    uint32_t* out;
    switch (which) {
        case 0: out = (uint32_t*)g_s8; break;
        case 1: out = (uint32_t*)g_t8; break;
        case 2: out = (uint32_t*)g_sw8; break;
        default: out = (uint32_t*)g_tw8; break;
    }
    size_t stride = (size_t)gridDim.x * blockDim.x;
    for (size_t i = (size_t)blockIdx.x * blockDim.x + threadIdx.x; i < n4; i += stride) {
        float4 v = in[i];
        out[i] = pack_e4m3_4(v.x * scale, v.y * scale, v.z * scale, v.w * scale);
    }
}

// ---------------- Kernel: exact fp32 target logit -----------------------------
__global__ void tgt_kernel(const float* __restrict__ student,
                           const float* __restrict__ sw,
                           const int* __restrict__ target) {
    int row = blockIdx.x;
    int t = target[row];
    int ct = (t < 0 || t >= VV) ? 0 : t;
    const float4* a = (const float4*)(student + (size_t)row * HS);
    const float4* b = (const float4*)(sw + (size_t)ct * HS);
    float p = 0.f;
    for (int k = threadIdx.x; k < HS / 4; k += blockDim.x) {
        float4 x = a[k]; float4 y = b[k];
        p += x.x * y.x + x.y * y.y + x.z * y.z + x.w * y.w;
    }
    __shared__ float sred[8];
    #pragma unroll
    for (int o = 16; o; o >>= 1) p += __shfl_down_sync(0xffffffffu, p, o);
    if ((threadIdx.x & 31) == 0) sred[threadIdx.x >> 5] = p;
    __syncthreads();
    if (threadIdx.x < 32) {
        p = (threadIdx.x < (blockDim.x >> 5)) ? sred[threadIdx.x] : 0.f;
        #pragma unroll
        for (int o = 16; o; o >>= 1) p += __shfl_down_sync(0xffffffffu, p, o);
        if (threadIdx.x == 0) g_tgt[row] = p;
    }
}

// ---------------- Kernel: two-phase dual FP8 MMA GEMM + row stats ------------
// Grid (16, 125). Block tile 128x256; 16 warps as 4m x 4n, warp tile 32x64.
// LDSM base addresses hoisted; per-kf offset composed with XOR (valid since
// pre-swizzle bases have bits 5-6 clear and kf*32 never touches bits 7-9).
__global__ __launch_bounds__(THREADS, 1) void main_kernel() {
    extern __shared__ char smem[];
    const uint32_t sb = smem_u32(smem);
    const int tid = threadIdx.x;
    const int wid = tid >> 5;
    const int lane = tid & 31;
    const int mw = wid & 3;        // 4 warps in m
    const int nw = wid >> 2;       // 4 warps in n
    const int rb = blockIdx.x * BM;
    const int vb = blockIdx.y * BN;

    const int q = tid & 7;     // 16B chunk within 128B row
    const int r0 = tid >> 3;   // base row 0..63

    float acc[2][8][4];        // 32x64 warp tile
    #pragma unroll
    for (int i = 0; i < 2; i++)
        #pragma unroll
        for (int j = 0; j < 8; j++)
            #pragma unroll
            for (int e = 0; e < 4; e++) acc[i][j][e] = 0.f;

    auto issue = [&](int kt, int s) {
        const bool tea = (kt >= KT_S);
        const int kk = tea ? (kt - KT_S) : kt;
        const uint8_t* Ab = tea ? g_t8 : g_s8;
        const uint8_t* Bb = tea ? g_tw8 : g_sw8;
        const int ldk = tea ? HT : HS;    // bytes per row (1B/elem)
        const uint32_t st = sb + s * STAGE_BYTES;
        #pragma unroll
        for (int c = 0; c < 2; c++) {
            int row = r0 + 64 * c;
            cp_async16(st + SWZ(row * 128 + q * 16),
                       Ab + (size_t)(rb + row) * ldk + kk * BK + q * 16);
        }
        #pragma unroll
        for (int c = 0; c < 4; c++) {
            int row = r0 + 64 * c;
            cp_async16(st + A_BYTES + SWZ(row * 128 + q * 16),
                       Bb + (size_t)(vb + row) * ldk + kk * BK + q * 16);
        }
        cp_commit();
    };

    // hoisted LDSM swizzled base offsets (kf composed via XOR in the loop)
    const int arow = mw * 32 + (lane & 15);
    const int brow = nw * 64 + (lane & 15);
    const int csel = (lane >> 4) * 16;
    uint32_t aoff[2], boff[4];
    #pragma unroll
    for (int mi = 0; mi < 2; mi++) aoff[mi] = SWZ((arow + mi * 16) * 128 + csel);
    #pragma unroll
    for (int np = 0; np < 4; np++) boff[np] = A_BYTES + SWZ((brow + np * 16) * 128 + csel);

    auto step = [&](int kt) __attribute__((always_inline)) {
        const int s = kt % STAGES;
        if (kt < NKT - 1) {
            asm volatile("cp.async.wait_group 1;" ::: "memory");
        } else {
            asm volatile("cp.async.wait_group 0;" ::: "memory");
        }
        __syncthreads();
        if (kt + 2 < NKT) issue(kt + 2, (kt + 2) % STAGES);

        const uint32_t st = sb + s * STAGE_BYTES;
        #pragma unroll
        for (int kf = 0; kf < 4; kf++) {   // kf covers 32 fp8 bytes
            const uint32_t ko = (uint32_t)kf * 32;
            uint32_t af[2][4], bfv[4][4];
            #pragma unroll
            for (int mi = 0; mi < 2; mi++)
                ldsm_x4(af[mi], st + (aoff[mi] ^ ko));
            #pragma unroll
            for (int np = 0; np < 4; np++)
                ldsm_x4(bfv[np], st + (boff[np] ^ ko));
            #pragma unroll
            for (int mi = 0; mi < 2; mi++)
                #pragma unroll
                for (int np = 0; np < 4; np++) {
                    mma16832(acc[mi][2 * np + 0], af[mi], bfv[np][0], bfv[np][2]);
                    mma16832(acc[mi][2 * np + 1], af[mi], bfv[np][1], bfv[np][3]);
                }
        }
    };

    issue(0, 0);
    issue(1, 1);

    // ---- phase 1: student ----
    for (int kt = 0; kt < KT_S; kt++) step(kt);

    // phase boundary: unscale logits, exp/ss stats, stash s (bf16) in smem.
    {
        const uint32_t lane_col_b = (uint32_t)(nw * 64 + (lane & 3) * 2) * 2;
        #pragma unroll
        for (int mi = 0; mi < 2; mi++) {
            #pragma unroll
            for (int hb = 0; hb < 2; hb++) {
                int row = mw * 32 + mi * 16 + (lane >> 2) + hb * 8;
                uint32_t rowoff = sb + SBUF_OFF + (uint32_t)row * SBUF_ROW + lane_col_b;
                float pe = 0.f, pss = 0.f;
                #pragma unroll
                for (int ni = 0; ni < 8; ni++) {
                    float s0 = acc[mi][ni][hb * 2 + 0] * ISCALE;
                    float s1 = acc[mi][ni][hb * 2 + 1] * ISCALE;
                    pe += __expf(s0) + __expf(s1);
                    pss += s0 * s0 + s1 * s1;
                    __nv_bfloat162 p = __floats2bfloat162_rn(s0, s1);
                    uint32_t pw = *(uint32_t*)&p;
                    asm volatile("st.shared.b32 [%0], %1;" :: "r"(rowoff + ni * 16), "r"(pw) : "memory");
                }
                #pragma unroll
                for (int o = 1; o < 4; o <<= 1) {
                    pe += __shfl_xor_sync(0xffffffffu, pe, o);
                    pss += __shfl_xor_sync(0xffffffffu, pss, o);
                }
                if ((lane & 3) == 0) {
                    atomicAdd(&g_sumexp[rb + row], pe);
                    atomicAdd(&g_ss[rb + row], pss);
                }
            }
        }
        #pragma unroll
        for (int i = 0; i < 2; i++)
            #pragma unroll
            for (int j = 0; j < 8; j++)
                #pragma unroll
                for (int e = 0; e < 4; e++) acc[i][j][e] = 0.f;
    }

    // ---- phase 2: teacher ----
    for (int kt = KT_S; kt < NKT; kt++) step(kt);

    // final epilogue: tt/st stats (s read back from smem, lane-private values).
    {
        const uint32_t lane_col_b = (uint32_t)(nw * 64 + (lane & 3) * 2) * 2;
        #pragma unroll
        for (int mi = 0; mi < 2; mi++) {
            #pragma unroll
            for (int hb = 0; hb < 2; hb++) {
                int row = mw * 32 + mi * 16 + (lane >> 2) + hb * 8;
                uint32_t rowoff = sb + SBUF_OFF + (uint32_t)row * SBUF_ROW + lane_col_b;
                float ptt = 0.f, pst = 0.f;
                #pragma unroll
                for (int ni = 0; ni < 8; ni++) {
                    uint32_t pw;
                    asm volatile("ld.shared.b32 %0, [%1];" : "=r"(pw) : "r"(rowoff + ni * 16));
                    __nv_bfloat162 p = *(__nv_bfloat162*)&pw;
                    float s0 = __bfloat162float(p.x);
                    float s1 = __bfloat162float(p.y);
                    float t0 = acc[mi][ni][hb * 2 + 0] * ISCALE;
                    float t1 = acc[mi][ni][hb * 2 + 1] * ISCALE;
                    ptt += t0 * t0 + t1 * t1;
                    pst += s0 * t0 + s1 * t1;
                }
                #pragma unroll
                for (int o = 1; o < 4; o <<= 1) {
                    ptt += __shfl_xor_sync(0xffffffffu, ptt, o);
                    pst += __shfl_xor_sync(0xffffffffu, pst, o);
                }
                if ((lane & 3) == 0) {
                    atomicAdd(&g_tt[rb + row], ptt);
                    atomicAdd(&g_st[rb + row], pst);
                }
            }
        }
    }
}

// ---------------- Kernel: final scalar loss ----------------------------------
__global__ void final_kernel(const int* __restrict__ target, float* __restrict__ out) {
    __shared__ float sh[8], ssf[8], snv[8];
    float hard = 0.f, soft = 0.f, nv = 0.f;
    for (int i = threadIdx.x; i < BT; i += blockDim.x) {
        int t = target[i];
        bool valid = (t != IGNORE_IDX);
        float lse = logf(g_sumexp[i]);
        if (valid) { hard += lse - g_tgt[i]; nv += 1.f; }
        float cs = g_st[i] * rsqrtf(g_ss[i] + 1e-12f) * rsqrtf(g_tt[i] + 1e-12f);
        soft += 1.f - cs;
    }
    #pragma unroll
    for (int o = 16; o; o >>= 1) {
        hard += __shfl_down_sync(0xffffffffu, hard, o);
        soft += __shfl_down_sync(0xffffffffu, soft, o);
        nv += __shfl_down_sync(0xffffffffu, nv, o);
    }
    int w = threadIdx.x >> 5, l = threadIdx.x & 31;
    if (l == 0) { sh[w] = hard; ssf[w] = soft; snv[w] = nv; }
    __syncthreads();
    if (threadIdx.x < 32) {
        int nw = blockDim.x >> 5;
        hard = (threadIdx.x < nw) ? sh[threadIdx.x] : 0.f;
        soft = (threadIdx.x < nw) ? ssf[threadIdx.x] : 0.f;
        nv = (threadIdx.x < nw) ? snv[threadIdx.x] : 0.f;
        #pragma unroll
        for (int o = 16; o; o >>= 1) {
            hard += __shfl_down_sync(0xffffffffu, hard, o);
            soft += __shfl_down_sync(0xffffffffu, soft, o);
            nv += __shfl_down_sync(0xffffffffu, nv, o);
        }
        if (threadIdx.x == 0)
            out[0] = 0.5f * hard / nv + 0.5f * soft / nv;
    }
}

// ---------------- launch ------------------------------------------------------
// Serial launch order (fork-join regressed in R15); main_kernel at ncu -s 5.
extern "C" void kernel_launch(void* const* d_in, const int* in_sizes, int n_in,
                              void* d_out, int out_size) {
    const float* student = (const float*)d_in[0];
    const float* teacher = (const float*)d_in[1];
    const int* target = (const int*)d_in[2];
    const float* sw = (const float*)d_in[3];
    const float* tw = (const float*)d_in[4];
    float* out = (float*)d_out;

    cudaFuncSetAttribute(main_kernel, cudaFuncAttributeMaxDynamicSharedMemorySize, SMEM_BYTES);

    cvt_kernel<<<2048, 256>>>((const float4*)student, 0, (size_t)BT * HS / 4, 1.0f);  // idx 0
    cvt_kernel<<<2048, 256>>>((const float4*)teacher, 1, (size_t)BT * HT / 4, 1.0f);  // idx 1
    cvt_kernel<<<4096, 256>>>((const float4*)sw, 2, (size_t)VV * HS / 4, WSCALE);     // idx 2
    cvt_kernel<<<4096, 256>>>((const float4*)tw, 3, (size_t)VV * HT / 4, WSCALE);     // idx 3
    tgt_kernel<<<BT, 128>>>(student, sw, target);                                     // idx 4
    dim3 grid(BT / BM, VV / BN);  // (16, 125)
    main_kernel<<<grid, THREADS, SMEM_BYTES>>>();                                     // idx 5
    final_kernel<<<1, 256>>>(target, out);                                            // idx 6
}